// round 1
// baseline (speedup 1.0000x reference)
#include <cuda_runtime.h>

#define NN 50000
#define EE 800000

// Scratch (no allocation allowed -> __device__ globals)
__device__ float g_h[NN * 128];
__device__ float g_agg[NN * 128];
__device__ int g_src[EE];
__device__ int g_dst[EE];
__device__ int g_csr[EE];
__device__ int g_cnt[NN];
__device__ int g_rowptr[NN + 1];
__device__ int g_cursor[NN];
__device__ float g_dinv[NN];
__device__ int g_is64;

// ---------------------------------------------------------------------------
// Edge dtype detection: int64 little-endian with values < 2^31 has every odd
// 32-bit word == 0. Random int32 node ids make that astronomically unlikely.
__global__ void detect_kernel(const void* ei) {
    if (threadIdx.x == 0) {
        const int* w = (const int*)ei;
        int all0 = 1;
#pragma unroll 1
        for (int i = 1; i < 256; i += 2) all0 &= (w[i] == 0);
        g_is64 = all0;
    }
}

__global__ void zero_cnt_kernel() {
    int i = blockIdx.x * blockDim.x + threadIdx.x;
    if (i < NN) g_cnt[i] = 0;
}

// Normalize edges to int32 + in-degree histogram (targets = edge_index[1]).
__global__ void convert_hist_kernel(const void* ei) {
    int i = blockIdx.x * blockDim.x + threadIdx.x;
    if (i >= EE) return;
    int s, d;
    if (g_is64) {
        const long long* p = (const long long*)ei;
        s = (int)p[i];
        d = (int)p[EE + i];
    } else {
        const int* p = (const int*)ei;
        s = p[i];
        d = p[EE + i];
    }
    g_src[i] = s;
    g_dst[i] = d;
    atomicAdd(&g_cnt[d], 1);
}

// Single-block exclusive scan over 50000 counts -> rowptr, cursor, dinv.
// deg = cnt + 1 (self loop), dinv = rsqrt(deg).
__global__ void scan_kernel() {
    __shared__ int sm[1024];
    const int per = (NN + 1023) / 1024;  // 49
    int tid = threadIdx.x;
    int base = tid * per;
    int s = 0;
    for (int i = 0; i < per; i++) {
        int idx = base + i;
        if (idx < NN) s += g_cnt[idx];
    }
    sm[tid] = s;
    __syncthreads();
    for (int d = 1; d < 1024; d <<= 1) {
        int v = (tid >= d) ? sm[tid - d] : 0;
        __syncthreads();
        sm[tid] += v;
        __syncthreads();
    }
    int run = sm[tid] - s;  // exclusive prefix
    for (int i = 0; i < per; i++) {
        int idx = base + i;
        if (idx < NN) {
            g_rowptr[idx] = run;
            g_cursor[idx] = run;
            g_dinv[idx] = rsqrtf((float)g_cnt[idx] + 1.0f);
            run += g_cnt[idx];
        }
    }
    if (tid == 1023) g_rowptr[NN] = sm[1023];
}

__global__ void scatter_kernel() {
    int i = blockIdx.x * blockDim.x + threadIdx.x;
    if (i >= EE) return;
    int d = g_dst[i];
    int p = atomicAdd(&g_cursor[d], 1);
    g_csr[p] = g_src[i];
}

// ---------------------------------------------------------------------------
// GEMM: [NN,128] x [128,128] -> [NN,128]. W resident in smem. 8 warps/block,
// each warp computes 4 rows x 128 cols (4 cols/lane), FFMA-bound.
// If B1 != null: B = [B0 (128x64) | B1 (128x64)], outputs split O0/O1 (64 cols
// each) with per-half bias + optional relu.
__global__ void __launch_bounds__(256, 2) gemm128_kernel(
    const float* __restrict__ X, const float* __restrict__ B0,
    const float* __restrict__ B1, const float* __restrict__ bias0,
    const float* __restrict__ bias1, float* __restrict__ O0,
    float* __restrict__ O1, int do_relu) {
    extern __shared__ float sm[];
    float* Wsm = sm;              // 128*128 floats
    float* xs = sm + 128 * 128;   // 8 warps * 4 rows * 128 floats
    int tid = threadIdx.x, w = tid >> 5, lane = tid & 31;

    for (int idx = tid; idx < 128 * 128; idx += 256) {
        float v;
        if (B1) {
            int k = idx >> 7, n = idx & 127;
            v = (n < 64) ? B0[(k << 6) + n] : B1[(k << 6) + n - 64];
        } else {
            v = B0[idx];
        }
        Wsm[idx] = v;
    }
    __syncthreads();

    int row0 = (blockIdx.x * 8 + w) * 4;
    if (row0 >= NN) return;
    float* xw = xs + w * 4 * 128;

#pragma unroll
    for (int r = 0; r < 4; r++) {
        int row = row0 + r;
        float4 v = (row < NN) ? *(const float4*)(X + row * 128 + lane * 4)
                              : make_float4(0.f, 0.f, 0.f, 0.f);
        *(float4*)(xw + r * 128 + lane * 4) = v;
    }
    __syncwarp();

    float4 a0 = make_float4(0.f, 0.f, 0.f, 0.f), a1 = a0, a2 = a0, a3 = a0;
#pragma unroll 16
    for (int k = 0; k < 128; k++) {
        float4 wv = *(float4*)(Wsm + k * 128 + lane * 4);
        float x0 = xw[0 * 128 + k];
        float x1 = xw[1 * 128 + k];
        float x2 = xw[2 * 128 + k];
        float x3 = xw[3 * 128 + k];
        a0.x += x0 * wv.x; a0.y += x0 * wv.y; a0.z += x0 * wv.z; a0.w += x0 * wv.w;
        a1.x += x1 * wv.x; a1.y += x1 * wv.y; a1.z += x1 * wv.z; a1.w += x1 * wv.w;
        a2.x += x2 * wv.x; a2.y += x2 * wv.y; a2.z += x2 * wv.z; a2.w += x2 * wv.w;
        a3.x += x3 * wv.x; a3.y += x3 * wv.y; a3.z += x3 * wv.z; a3.w += x3 * wv.w;
    }

    int col = lane * 4;
    float4 bi = make_float4(0.f, 0.f, 0.f, 0.f);
    if (bias0) {
        if (B1)
            bi = (col < 64) ? *(const float4*)(bias0 + col)
                            : *(const float4*)(bias1 + col - 64);
        else
            bi = *(const float4*)(bias0 + col);
    }
    float4 accs[4] = {a0, a1, a2, a3};
#pragma unroll
    for (int r = 0; r < 4; r++) {
        int row = row0 + r;
        if (row >= NN) break;
        float4 o = accs[r];
        o.x += bi.x; o.y += bi.y; o.z += bi.z; o.w += bi.w;
        if (do_relu) {
            o.x = fmaxf(o.x, 0.f); o.y = fmaxf(o.y, 0.f);
            o.z = fmaxf(o.z, 0.f); o.w = fmaxf(o.w, 0.f);
        }
        if (B1) {
            if (col < 64)
                *(float4*)(O0 + row * 64 + col) = o;
            else
                *(float4*)(O1 + row * 64 + col - 64) = o;
        } else {
            *(float4*)(O0 + row * 128 + col) = o;
        }
    }
}

// ---------------------------------------------------------------------------
// Aggregation: OUT[c] = dinv[c]*(sum_{r in in(c)} dinv[r]*H[r]) + dinv[c]^2*H[c]
// One warp per node, 4 channels per lane (float4). Optional bias+relu epilogue.
__global__ void agg_kernel(const float* __restrict__ H, float* __restrict__ OUT,
                           const float* __restrict__ bias, int do_relu) {
    int gw = (blockIdx.x * blockDim.x + threadIdx.x) >> 5;
    if (gw >= NN) return;
    int lane = threadIdx.x & 31;
    int node = gw;
    int s = g_rowptr[node], e = g_rowptr[node + 1];
    float ax = 0.f, ay = 0.f, az = 0.f, aw = 0.f;
    for (int j = s; j < e; j++) {
        int src = g_csr[j];
        float wgt = g_dinv[src];
        float4 v = *(const float4*)(H + src * 128 + lane * 4);
        ax += wgt * v.x; ay += wgt * v.y; az += wgt * v.z; aw += wgt * v.w;
    }
    float dc = g_dinv[node];
    float dc2 = dc * dc;
    float4 sv = *(const float4*)(H + node * 128 + lane * 4);
    ax = dc * ax + dc2 * sv.x;
    ay = dc * ay + dc2 * sv.y;
    az = dc * az + dc2 * sv.z;
    aw = dc * aw + dc2 * sv.w;
    if (bias) {
        float4 bi = *(const float4*)(bias + lane * 4);
        ax += bi.x; ay += bi.y; az += bi.z; aw += bi.w;
    }
    if (do_relu) {
        ax = fmaxf(ax, 0.f); ay = fmaxf(ay, 0.f);
        az = fmaxf(az, 0.f); aw = fmaxf(aw, 0.f);
    }
    float4 o = make_float4(ax, ay, az, aw);
    *(float4*)(OUT + node * 128 + lane * 4) = o;
}

// ---------------------------------------------------------------------------
extern "C" void kernel_launch(void* const* d_in, const int* in_sizes, int n_in,
                              void* d_out, int out_size) {
    const float* x = (const float*)d_in[0];
    const void* ei = d_in[1];
    const float* W1 = (const float*)d_in[2];
    const float* b1 = (const float*)d_in[3];
    const float* W2 = (const float*)d_in[4];
    const float* b2 = (const float*)d_in[5];
    const float* W3 = (const float*)d_in[6];
    const float* b3 = (const float*)d_in[7];
    float* out = (float*)d_out;

    float* ph;
    float* pagg;
    cudaGetSymbolAddress((void**)&ph, g_h);
    cudaGetSymbolAddress((void**)&pagg, g_agg);

    const size_t smem = (128 * 128 + 8 * 4 * 128) * sizeof(float);  // 80 KB
    cudaFuncSetAttribute(gemm128_kernel,
                         cudaFuncAttributeMaxDynamicSharedMemorySize,
                         (int)smem);

    // CSR build (recomputed every replay; graph-capture safe, no allocs)
    detect_kernel<<<1, 32>>>(ei);
    zero_cnt_kernel<<<(NN + 255) / 256, 256>>>();
    convert_hist_kernel<<<(EE + 255) / 256, 256>>>(ei);
    scan_kernel<<<1, 1024>>>();
    scatter_kernel<<<(EE + 255) / 256, 256>>>();

    int gblocks = (NN + 31) / 32;
    int ablocks = (NN * 32 + 255) / 256;

    // h = x @ W1
    gemm128_kernel<<<gblocks, 256, smem>>>(x, W1, nullptr, nullptr, nullptr,
                                           ph, nullptr, 0);
    // hidden = relu(A h + b1)
    agg_kernel<<<ablocks, 256>>>(ph, pagg, b1, 1);
    // aggH = A hidden  (shared by both heads)
    agg_kernel<<<ablocks, 256>>>(pagg, ph, nullptr, 0);
    // x1 = relu(aggH @ W2 + b2), x2 = relu(aggH @ W3 + b3)
    gemm128_kernel<<<gblocks, 256, smem>>>(ph, W2, W3, b2, b3, out,
                                           out + (size_t)NN * 64, 1);
}

// round 5
// speedup vs baseline: 1.4122x; 1.4122x over previous
#include <cuda_runtime.h>

#define NN 50000
#define EE 800000
#define SCAN_B 256
#define NBLK ((NN + SCAN_B - 1) / SCAN_B)  // 196

// Scratch (no allocation allowed -> __device__ globals)
__device__ float g_h[NN * 128];
__device__ float g_agg[NN * 128];
__device__ int g_src[EE];
__device__ int g_dst[EE];
__device__ int g_csr[EE];
__device__ int g_cnt[NN];
__device__ int g_rowptr[NN + 1];
__device__ int g_cursor[NN];
__device__ float g_dinv[NN];
__device__ int g_is64;
__device__ int g_bsum[NBLK];
__device__ int g_boff[NBLK];

// ---------------------------------------------------------------------------
// Edge dtype detection: int64 little-endian with values < 2^31 has every odd
// 32-bit word == 0. Random int32 node ids make that astronomically unlikely.
__global__ void detect_kernel(const void* ei) {
    if (threadIdx.x == 0) {
        const int* w = (const int*)ei;
        int all0 = 1;
#pragma unroll 1
        for (int i = 1; i < 256; i += 2) all0 &= (w[i] == 0);
        g_is64 = all0;
    }
}

__global__ void zero_cnt_kernel() {
    int i = blockIdx.x * blockDim.x + threadIdx.x;
    if (i < NN) g_cnt[i] = 0;
}

// Normalize edges to int32 + in-degree histogram (targets = edge_index[1]).
__global__ void convert_hist_kernel(const void* ei) {
    int i = blockIdx.x * blockDim.x + threadIdx.x;
    if (i >= EE) return;
    int s, d;
    if (g_is64) {
        const long long* p = (const long long*)ei;
        s = (int)p[i];
        d = (int)p[EE + i];
    } else {
        const int* p = (const int*)ei;
        s = p[i];
        d = p[EE + i];
    }
    g_src[i] = s;
    g_dst[i] = d;
    atomicAdd(&g_cnt[d], 1);
}

// ---------------------------------------------------------------------------
// Hierarchical exclusive scan over g_cnt (3 tiny kernels, all-SM parallel).
__global__ void bsum_kernel() {
    __shared__ int sw[8];
    int i = blockIdx.x * SCAN_B + threadIdx.x;
    int v = (i < NN) ? g_cnt[i] : 0;
#pragma unroll
    for (int o = 16; o > 0; o >>= 1) v += __shfl_down_sync(~0u, v, o);
    int lane = threadIdx.x & 31, w = threadIdx.x >> 5;
    if (lane == 0) sw[w] = v;
    __syncthreads();
    if (threadIdx.x < 8) {
        int s = sw[threadIdx.x];
#pragma unroll
        for (int o = 4; o > 0; o >>= 1) s += __shfl_down_sync(0xff, s, o);
        if (threadIdx.x == 0) g_bsum[blockIdx.x] = s;
    }
}

__global__ void boff_kernel() {
    // 256 threads, exclusive scan over NBLK (<=256) block sums.
    __shared__ int sm[256];
    int tid = threadIdx.x;
    int v = (tid < NBLK) ? g_bsum[tid] : 0;
    sm[tid] = v;
    __syncthreads();
    for (int d = 1; d < 256; d <<= 1) {
        int t = (tid >= d) ? sm[tid - d] : 0;
        __syncthreads();
        sm[tid] += t;
        __syncthreads();
    }
    if (tid < NBLK) g_boff[tid] = sm[tid] - v;  // exclusive
    if (tid == 255) g_rowptr[NN] = sm[255];
}

__global__ void scanwrite_kernel() {
    __shared__ int swarp[8];
    int tid = threadIdx.x;
    int i = blockIdx.x * SCAN_B + tid;
    int c = (i < NN) ? g_cnt[i] : 0;
    // warp inclusive scan
    int v = c;
    int lane = tid & 31, w = tid >> 5;
#pragma unroll
    for (int o = 1; o < 32; o <<= 1) {
        int t = __shfl_up_sync(~0u, v, o);
        if (lane >= o) v += t;
    }
    if (lane == 31) swarp[w] = v;
    __syncthreads();
    if (tid < 8) {
        int s = swarp[tid];
        // serial exclusive over 8 entries via shfl scan
#pragma unroll
        for (int o = 1; o < 8; o <<= 1) {
            int t = __shfl_up_sync(0xff, s, o);
            if (tid >= o) s += t;
        }
        swarp[tid] = s;
    }
    __syncthreads();
    int excl = v - c + (w > 0 ? swarp[w - 1] : 0) + g_boff[blockIdx.x];
    if (i < NN) {
        g_rowptr[i] = excl;
        g_cursor[i] = excl;
        g_dinv[i] = rsqrtf((float)c + 1.0f);
    }
}

__global__ void scatter_kernel() {
    int i = blockIdx.x * blockDim.x + threadIdx.x;
    if (i >= EE) return;
    int d = g_dst[i];
    int p = atomicAdd(&g_cursor[d], 1);
    g_csr[p] = g_src[i];
}

// ---------------------------------------------------------------------------
// GEMM: [NN,128] x [128,128] -> [NN,128]. W resident in smem. 8 warps/block,
// each warp computes 4 rows x 128 cols (4 cols/lane), FFMA-bound.
// If B1 != null: B = [B0 (128x64) | B1 (128x64)], outputs split O0/O1 (64 cols
// each) with per-half bias + optional relu.
__global__ void __launch_bounds__(256, 2) gemm128_kernel(
    const float* __restrict__ X, const float* __restrict__ B0,
    const float* __restrict__ B1, const float* __restrict__ bias0,
    const float* __restrict__ bias1, float* __restrict__ O0,
    float* __restrict__ O1, int do_relu) {
    extern __shared__ float sm[];
    float* Wsm = sm;              // 128*128 floats
    float* xs = sm + 128 * 128;   // 8 warps * 4 rows * 128 floats
    int tid = threadIdx.x, w = tid >> 5, lane = tid & 31;

    for (int idx = tid; idx < 128 * 128; idx += 256) {
        float v;
        if (B1) {
            int k = idx >> 7, n = idx & 127;
            v = (n < 64) ? B0[(k << 6) + n] : B1[(k << 6) + n - 64];
        } else {
            v = B0[idx];
        }
        Wsm[idx] = v;
    }
    __syncthreads();

    int row0 = (blockIdx.x * 8 + w) * 4;
    if (row0 >= NN) return;
    float* xw = xs + w * 4 * 128;

#pragma unroll
    for (int r = 0; r < 4; r++) {
        int row = row0 + r;
        float4 v = (row < NN) ? *(const float4*)(X + row * 128 + lane * 4)
                              : make_float4(0.f, 0.f, 0.f, 0.f);
        *(float4*)(xw + r * 128 + lane * 4) = v;
    }
    __syncwarp();

    float4 a0 = make_float4(0.f, 0.f, 0.f, 0.f), a1 = a0, a2 = a0, a3 = a0;
#pragma unroll 16
    for (int k = 0; k < 128; k++) {
        float4 wv = *(float4*)(Wsm + k * 128 + lane * 4);
        float x0 = xw[0 * 128 + k];
        float x1 = xw[1 * 128 + k];
        float x2 = xw[2 * 128 + k];
        float x3 = xw[3 * 128 + k];
        a0.x += x0 * wv.x; a0.y += x0 * wv.y; a0.z += x0 * wv.z; a0.w += x0 * wv.w;
        a1.x += x1 * wv.x; a1.y += x1 * wv.y; a1.z += x1 * wv.z; a1.w += x1 * wv.w;
        a2.x += x2 * wv.x; a2.y += x2 * wv.y; a2.z += x2 * wv.z; a2.w += x2 * wv.w;
        a3.x += x3 * wv.x; a3.y += x3 * wv.y; a3.z += x3 * wv.z; a3.w += x3 * wv.w;
    }

    int col = lane * 4;
    float4 bi = make_float4(0.f, 0.f, 0.f, 0.f);
    if (bias0) {
        if (B1)
            bi = (col < 64) ? *(const float4*)(bias0 + col)
                            : *(const float4*)(bias1 + col - 64);
        else
            bi = *(const float4*)(bias0 + col);
    }
    float4 accs[4] = {a0, a1, a2, a3};
#pragma unroll
    for (int r = 0; r < 4; r++) {
        int row = row0 + r;
        if (row >= NN) break;
        float4 o = accs[r];
        o.x += bi.x; o.y += bi.y; o.z += bi.z; o.w += bi.w;
        if (do_relu) {
            o.x = fmaxf(o.x, 0.f); o.y = fmaxf(o.y, 0.f);
            o.z = fmaxf(o.z, 0.f); o.w = fmaxf(o.w, 0.f);
        }
        if (B1) {
            if (col < 64)
                *(float4*)(O0 + row * 64 + col) = o;
            else
                *(float4*)(O1 + row * 64 + col - 64) = o;
        } else {
            *(float4*)(O0 + row * 128 + col) = o;
        }
    }
}

// ---------------------------------------------------------------------------
// Aggregation: OUT[c] = dinv[c]*(sum_{r in in(c)} dinv[r]*H[r]) + dinv[c]^2*H[c]
// One warp per node, 4 channels per lane (float4). Optional bias+relu epilogue.
__global__ void agg_kernel(const float* __restrict__ H, float* __restrict__ OUT,
                           const float* __restrict__ bias, int do_relu) {
    int gw = (blockIdx.x * blockDim.x + threadIdx.x) >> 5;
    if (gw >= NN) return;
    int lane = threadIdx.x & 31;
    int node = gw;
    int s = g_rowptr[node], e = g_rowptr[node + 1];
    float ax = 0.f, ay = 0.f, az = 0.f, aw = 0.f;
    for (int j = s; j < e; j++) {
        int src = g_csr[j];
        float wgt = g_dinv[src];
        float4 v = *(const float4*)(H + src * 128 + lane * 4);
        ax += wgt * v.x; ay += wgt * v.y; az += wgt * v.z; aw += wgt * v.w;
    }
    float dc = g_dinv[node];
    float dc2 = dc * dc;
    float4 sv = *(const float4*)(H + node * 128 + lane * 4);
    ax = dc * ax + dc2 * sv.x;
    ay = dc * ay + dc2 * sv.y;
    az = dc * az + dc2 * sv.z;
    aw = dc * aw + dc2 * sv.w;
    if (bias) {
        float4 bi = *(const float4*)(bias + lane * 4);
        ax += bi.x; ay += bi.y; az += bi.z; aw += bi.w;
    }
    if (do_relu) {
        ax = fmaxf(ax, 0.f); ay = fmaxf(ay, 0.f);
        az = fmaxf(az, 0.f); aw = fmaxf(aw, 0.f);
    }
    float4 o = make_float4(ax, ay, az, aw);
    *(float4*)(OUT + node * 128 + lane * 4) = o;
}

// ---------------------------------------------------------------------------
extern "C" void kernel_launch(void* const* d_in, const int* in_sizes, int n_in,
                              void* d_out, int out_size) {
    const float* x = (const float*)d_in[0];
    const void* ei = d_in[1];
    const float* W1 = (const float*)d_in[2];
    const float* b1 = (const float*)d_in[3];
    const float* W2 = (const float*)d_in[4];
    const float* b2 = (const float*)d_in[5];
    const float* W3 = (const float*)d_in[6];
    const float* b3 = (const float*)d_in[7];
    float* out = (float*)d_out;

    float* ph;
    float* pagg;
    cudaGetSymbolAddress((void**)&ph, g_h);
    cudaGetSymbolAddress((void**)&pagg, g_agg);

    const size_t smem = (128 * 128 + 8 * 4 * 128) * sizeof(float);  // 80 KB
    cudaFuncSetAttribute(gemm128_kernel,
                         cudaFuncAttributeMaxDynamicSharedMemorySize,
                         (int)smem);

    // CSR build (recomputed every replay; graph-capture safe, no allocs)
    detect_kernel<<<1, 32>>>(ei);
    zero_cnt_kernel<<<(NN + 255) / 256, 256>>>();
    convert_hist_kernel<<<(EE + 255) / 256, 256>>>(ei);
    bsum_kernel<<<NBLK, SCAN_B>>>();
    boff_kernel<<<1, 256>>>();
    scanwrite_kernel<<<NBLK, SCAN_B>>>();
    scatter_kernel<<<(EE + 255) / 256, 256>>>();

    int gblocks = (NN + 31) / 32;
    int ablocks = (NN * 32 + 255) / 256;

    // h = x @ W1
    gemm128_kernel<<<gblocks, 256, smem>>>(x, W1, nullptr, nullptr, nullptr,
                                           ph, nullptr, 0);
    // hidden = relu(A h + b1)
    agg_kernel<<<ablocks, 256>>>(ph, pagg, b1, 1);
    // aggH = A hidden  (shared by both heads)
    agg_kernel<<<ablocks, 256>>>(pagg, ph, nullptr, 0);
    // x1 = relu(aggH @ W2 + b2), x2 = relu(aggH @ W3 + b3)
    gemm128_kernel<<<gblocks, 256, smem>>>(ph, W2, W3, b2, b3, out,
                                           out + (size_t)NN * 64, 1);
}